// round 13
// baseline (speedup 1.0000x reference)
#include <cuda_runtime.h>
#include <cuda_bf16.h>

// ---------------------------------------------------------------------------
// GAT (2 layers, heads=1) on GB300 — R13: FFMA2 proj, fused scan, 8 launches,
// single-pass softmax weights (no max subtraction; logits are O(5)).
// ---------------------------------------------------------------------------

#define NMAX 50000
#define EMAX 1200000
#define C    64
#define SH_E 96    // max in-degree on fast path (Poisson(24); fallback correct anyway)

// -------------------- scratch (device globals; no allocs) ------------------
__device__ float g_hsrc[NMAX * C];
__device__ float g_lin [NMAX * C];
__device__ float g_h   [NMAX * C];
__device__ float g_asrc[NMAX];
__device__ float g_adst[NMAX];
__device__ int   g_deg   [NMAX];
__device__ int   g_rowptr[NMAX + 1];
__device__ int   g_cursor[NMAX];
__device__ int   g_esrc  [EMAX];
__device__ int   g_is64;

// ---------------------------- f32x2 helpers ---------------------------------
__device__ __forceinline__ unsigned long long splat2(float x) {
    unsigned long long r;
    asm("mov.b64 %0, {%1, %1};" : "=l"(r) : "f"(x));
    return r;
}
__device__ __forceinline__ void fma2(unsigned long long& acc,
                                     unsigned long long a, unsigned long long b) {
    asm("fma.rn.f32x2 %0, %1, %2, %0;" : "+l"(acc) : "l"(a), "l"(b));
}
__device__ __forceinline__ float2 unpk2(unsigned long long p) {
    float lo, hi;
    asm("mov.b64 {%0, %1}, %2;" : "=f"(lo), "=f"(hi) : "l"(p));
    return make_float2(lo, hi);
}

// ------------------------ init: zero deg + dtype detect ---------------------
__global__ void init_kernel(const long long* __restrict__ ei, int N) {
    int i = blockIdx.x * blockDim.x + threadIdx.x;
    if (i < N) g_deg[i] = 0;
    if (i == 0) {
        int is64 = 1;
        for (int k = 0; k < 64; k++) {
            long long v = ei[k];
            if (v < 0 || v >= N) { is64 = 0; break; }
        }
        g_is64 = is64;
    }
}

__device__ __forceinline__ int load_edge(const void* ei, long long idx, int is64) {
    if (is64) return (int)((const long long*)ei)[idx];
    return ((const int*)ei)[idx];
}

// -------------------------- CSR construction -------------------------------
__global__ void hist_kernel(const void* __restrict__ ei, int E, int N) {
    int e = blockIdx.x * blockDim.x + threadIdx.x;
    if (e < E) {
        int d = load_edge(ei, (long long)E + e, g_is64);
        if ((unsigned)d < (unsigned)N) atomicAdd(&g_deg[d], 1);
    }
}

// single-block fused exclusive scan: g_deg -> g_rowptr/g_cursor, rowptr[N]=E
__global__ __launch_bounds__(1024)
void scan_fused_kernel(int N, int E) {
    __shared__ int warp_sums[32];
    __shared__ int s_carry;
    int tid = threadIdx.x;
    int lane = tid & 31, wid = tid >> 5;
    if (tid == 0) s_carry = 0;
    __syncthreads();
    int nIter = (N + 1023) >> 10;
    for (int it = 0; it < nIter; it++) {
        int i = it * 1024 + tid;
        int v = (i < N) ? g_deg[i] : 0;
        int x = v;
#pragma unroll
        for (int o = 1; o < 32; o <<= 1) {
            int t = __shfl_up_sync(0xffffffff, x, o);
            if (lane >= o) x += t;
        }
        if (lane == 31) warp_sums[wid] = x;
        __syncthreads();
        if (wid == 0) {
            int s = warp_sums[lane];
#pragma unroll
            for (int o = 1; o < 32; o <<= 1) {
                int t = __shfl_up_sync(0xffffffff, s, o);
                if (lane >= o) s += t;
            }
            warp_sums[lane] = s;
        }
        __syncthreads();
        int base = s_carry + (wid ? warp_sums[wid - 1] : 0);
        int excl = base + x - v;
        if (i < N) { g_rowptr[i] = excl; g_cursor[i] = excl; }
        __syncthreads();
        if (tid == 1023) s_carry = base + x;
        __syncthreads();
    }
    if (tid == 0) g_rowptr[N] = E;
}

__global__ void scatter_kernel(const void* __restrict__ ei, int E, int N) {
    int e = blockIdx.x * blockDim.x + threadIdx.x;
    if (e < E) {
        int is64 = g_is64;
        int d = load_edge(ei, (long long)E + e, is64);
        int s = load_edge(ei, e, is64);
        if ((unsigned)d < (unsigned)N && (unsigned)s < (unsigned)N) {
            int pos = atomicAdd(&g_cursor[d], 1);
            if ((unsigned)pos < (unsigned)E) g_esrc[pos] = s;
        }
    }
}

// --------------------------- fused projection -------------------------------
// Per node: h_src row (x@Wsrc), lin row (x@Wlin), a_src, a_dst.
// v = Wdst@attd folded per-block; GEMMs use packed fma.rn.f32x2.
__global__ __launch_bounds__(256)
void proj_kernel(const float* __restrict__ xin_param,
                 const float* __restrict__ Wsrc,
                 const float* __restrict__ Wdst,
                 const float* __restrict__ Wlin,
                 const float* __restrict__ att_src,
                 const float* __restrict__ att_dst,
                 int from_gh, int N) {
    __shared__ __align__(16) float sWs[C * C];
    __shared__ __align__(16) float sWl[C * C];
    __shared__ float sAtt[C];
    __shared__ float sV[C];
    for (int i = threadIdx.x; i < C * C; i += 256) { sWs[i] = Wsrc[i]; sWl[i] = Wlin[i]; }
    if (threadIdx.x < C) {
        int k = threadIdx.x;
        float a = 0.f;
#pragma unroll 8
        for (int j = 0; j < C; j++) a += Wdst[k * C + j] * att_dst[j];
        sV[k] = a;
        sAtt[k] = att_src[k];
    }
    __syncthreads();

    int n = blockIdx.x * 256 + threadIdx.x;
    if (n >= N) return;

    const float* xin = from_gh ? g_h : xin_param;
    float xr[C];
    const float4* xp = (const float4*)(xin + (size_t)n * C);
#pragma unroll
    for (int k = 0; k < C / 4; k++) {
        float4 t = xp[k];
        xr[4 * k] = t.x; xr[4 * k + 1] = t.y; xr[4 * k + 2] = t.z; xr[4 * k + 3] = t.w;
    }

    float ad = 0.f;
#pragma unroll
    for (int k = 0; k < C; k++) ad += xr[k] * sV[k];
    g_adst[n] = ad;

    // ---- h_src = xr @ Wsrc (f32x2), a_src = h_src . att_src ----
    float as = 0.f;
#pragma unroll
    for (int jc = 0; jc < C; jc += 16) {
        unsigned long long acc2[8];
#pragma unroll
        for (int j = 0; j < 8; j++) acc2[j] = 0ULL;
#pragma unroll
        for (int k = 0; k < C; k++) {
            unsigned long long xv2 = splat2(xr[k]);
            const ulonglong2* wr = (const ulonglong2*)(sWs + k * C + jc);
#pragma unroll
            for (int j4 = 0; j4 < 4; j4++) {
                ulonglong2 w = wr[j4];
                fma2(acc2[2 * j4],     xv2, w.x);
                fma2(acc2[2 * j4 + 1], xv2, w.y);
            }
        }
        float4* hp = (float4*)(g_hsrc + (size_t)n * C + jc);
#pragma unroll
        for (int j4 = 0; j4 < 4; j4++) {
            float2 p0 = unpk2(acc2[2 * j4]);
            float2 p1 = unpk2(acc2[2 * j4 + 1]);
            hp[j4] = make_float4(p0.x, p0.y, p1.x, p1.y);
            as += p0.x * sAtt[jc + 4 * j4]     + p0.y * sAtt[jc + 4 * j4 + 1]
                + p1.x * sAtt[jc + 4 * j4 + 2] + p1.y * sAtt[jc + 4 * j4 + 3];
        }
    }
    g_asrc[n] = as;

    // ---- lin = xr @ Wlin (f32x2) ----
#pragma unroll
    for (int jc = 0; jc < C; jc += 16) {
        unsigned long long acc2[8];
#pragma unroll
        for (int j = 0; j < 8; j++) acc2[j] = 0ULL;
#pragma unroll
        for (int k = 0; k < C; k++) {
            unsigned long long xv2 = splat2(xr[k]);
            const ulonglong2* wr = (const ulonglong2*)(sWl + k * C + jc);
#pragma unroll
            for (int j4 = 0; j4 < 4; j4++) {
                ulonglong2 w = wr[j4];
                fma2(acc2[2 * j4],     xv2, w.x);
                fma2(acc2[2 * j4 + 1], xv2, w.y);
            }
        }
        float4* lp = (float4*)(g_lin + (size_t)n * C + jc);
#pragma unroll
        for (int j4 = 0; j4 < 4; j4++) {
            float2 p0 = unpk2(acc2[2 * j4]);
            float2 p1 = unpk2(acc2[2 * j4 + 1]);
            lp[j4] = make_float4(p0.x, p0.y, p1.x, p1.y);
        }
    }
}

// ------------------------- edge aggregation ---------------------------------
// One warp per dst node. Single pass: w=exp(lrelu(e)) -> shared (packed with s),
// warp-sum. Gather pass: lanes own 2 columns; acc += w*h_src[s]. Epilogue fuses
// 1/sum, bias, residual, ReLU.
__global__ __launch_bounds__(256)
void edge_kernel(const float* __restrict__ bias,
                 const float* __restrict__ blin,
                 float* __restrict__ out_param,
                 int to_gh, int N) {
    __shared__ int2 sh_sw[8][SH_E];
    int wid  = threadIdx.x >> 5;
    int lane = threadIdx.x & 31;
    int n = blockIdx.x * 8 + wid;
    if (n >= N) return;

    int start = g_rowptr[n], end = g_rowptr[n + 1];
    int deg = end - start;

    float2 acc = make_float2(0.f, 0.f);
    float invs = 0.f;

    if (deg > 0) {
        float adn = g_adst[n];
        const float2* hp = (const float2*)g_hsrc;

        if (deg <= SH_E) {
            float sum = 0.f;
            for (int i = lane; i < deg; i += 32) {
                int s = g_esrc[start + i];
                float ev = g_asrc[s] + adn;
                ev = (ev >= 0.f) ? ev : 0.2f * ev;
                float w = __expf(ev);
                sh_sw[wid][i] = make_int2(s, __float_as_int(w));
                sum += w;
            }
#pragma unroll
            for (int o = 16; o > 0; o >>= 1) sum += __shfl_xor_sync(0xffffffff, sum, o);
            __syncwarp();

#pragma unroll 8
            for (int i = 0; i < deg; i++) {
                int2 sw = sh_sw[wid][i];
                float w = __int_as_float(sw.y);
                float2 hv = hp[(size_t)sw.x * 32 + lane];
                acc.x += w * hv.x;
                acc.y += w * hv.y;
            }
            invs = 1.f / sum;
        } else {
            float sum = 0.f;
            for (int i = lane; i < deg; i += 32) {
                int s = g_esrc[start + i];
                float ev = g_asrc[s] + adn;
                ev = (ev >= 0.f) ? ev : 0.2f * ev;
                sum += __expf(ev);
            }
#pragma unroll
            for (int o = 16; o > 0; o >>= 1) sum += __shfl_xor_sync(0xffffffff, sum, o);
            for (int i = 0; i < deg; i++) {
                int s = g_esrc[start + i];
                float ev = g_asrc[s] + adn;
                ev = (ev >= 0.f) ? ev : 0.2f * ev;
                float w = __expf(ev);
                float2 hv = hp[(size_t)s * 32 + lane];
                acc.x += w * hv.x;
                acc.y += w * hv.y;
            }
            invs = 1.f / sum;
        }
    }

    int c0 = 2 * lane;
    float2 lv = ((const float2*)(g_lin + (size_t)n * C))[lane];
    float v0 = acc.x * invs + bias[c0]     + lv.x + blin[c0];
    float v1 = acc.y * invs + bias[c0 + 1] + lv.y + blin[c0 + 1];
    v0 = fmaxf(v0, 0.f);
    v1 = fmaxf(v1, 0.f);
    float* op = to_gh ? g_h : out_param;
    ((float2*)(op + (size_t)n * C))[lane] = make_float2(v0, v1);
}

// ------------------------------- launch -------------------------------------
extern "C" void kernel_launch(void* const* d_in, const int* in_sizes, int n_in,
                              void* d_out, int out_size) {
    const float* x     = (const float*)d_in[0];
    const void*  ei    = d_in[1];
    const float* W1s   = (const float*)d_in[2];
    const float* W1d   = (const float*)d_in[3];
    const float* att1s = (const float*)d_in[4];
    const float* att1d = (const float*)d_in[5];
    const float* b1    = (const float*)d_in[6];
    const float* Wl1   = (const float*)d_in[7];
    const float* bl1   = (const float*)d_in[8];
    const float* W2s   = (const float*)d_in[9];
    const float* W2d   = (const float*)d_in[10];
    const float* att2s = (const float*)d_in[11];
    const float* att2d = (const float*)d_in[12];
    const float* b2    = (const float*)d_in[13];
    const float* Wl2   = (const float*)d_in[14];
    const float* bl2   = (const float*)d_in[15];
    float*       out   = (float*)d_out;

    int N = in_sizes[0] / C;         // 50000
    int E = in_sizes[1] / 2;         // 1200000

    int nbN = (N + 255) / 256;
    int nbE = (E + 255) / 256;
    int nbW = (N + 7) / 8;

    // ---- CSR build (shared by both layers): 4 launches ----
    init_kernel<<<nbN, 256>>>((const long long*)ei, N);
    hist_kernel<<<nbE, 256>>>(ei, E, N);
    scan_fused_kernel<<<1, 1024>>>(N, E);
    scatter_kernel<<<nbE, 256>>>(ei, E, N);

    // ---- layer 1: x -> g_h ----
    proj_kernel<<<nbN, 256>>>(x, W1s, W1d, Wl1, att1s, att1d, /*from_gh=*/0, N);
    edge_kernel<<<nbW, 256>>>(b1, bl1, out, /*to_gh=*/1, N);

    // ---- layer 2: g_h -> out ----
    proj_kernel<<<nbN, 256>>>(x, W2s, W2d, Wl2, att2s, att2d, /*from_gh=*/1, N);
    edge_kernel<<<nbW, 256>>>(b2, bl2, out, /*to_gh=*/0, N);
}

// round 14
// speedup vs baseline: 1.2698x; 1.2698x over previous
#include <cuda_runtime.h>
#include <cuda_bf16.h>

// ---------------------------------------------------------------------------
// GAT (2 layers, heads=1) on GB300 — R14.
// R12 structure (known 215us) + parallel dtype-detect (-20us), folded prep_v,
// single-pass softmax edge kernel. FFMA2 proj and fused scan REVERTED (R13
// post-mortem: both regressed).
// ---------------------------------------------------------------------------

#define NMAX 50000
#define EMAX 1200000
#define C    64
#define SH_E 256   // max in-degree on fast shared path (Poisson(24) -> never exceeded)

// -------------------- scratch (device globals; no allocs) ------------------
__device__ float g_hsrc[NMAX * C];
__device__ float g_lin [NMAX * C];
__device__ float g_h   [NMAX * C];
__device__ float g_asrc[NMAX];
__device__ float g_adst[NMAX];
__device__ int   g_deg   [NMAX];
__device__ int   g_rowptr[NMAX + 1];
__device__ int   g_cursor[NMAX];
__device__ int   g_esrc  [EMAX];
__device__ int   g_bsums [64];
__device__ int   g_is64;

// ------------------ init: zero deg + PARALLEL dtype detect ------------------
// int32 data misread as int64 pairs two random indices -> almost surely >= N.
// One warp checks 64 values in parallel (2 per lane) instead of a serial loop.
__global__ void init_kernel(const long long* __restrict__ ei, int N) {
    int i = blockIdx.x * blockDim.x + threadIdx.x;
    if (i < N) g_deg[i] = 0;
    if (blockIdx.x == 0 && threadIdx.x < 32) {
        long long v0 = ei[threadIdx.x];
        long long v1 = ei[32 + threadIdx.x];
        int bad = (v0 < 0 || v0 >= N || v1 < 0 || v1 >= N) ? 1 : 0;
        unsigned m = __ballot_sync(0xffffffff, bad);
        if (threadIdx.x == 0) g_is64 = (m == 0u) ? 1 : 0;
    }
}

__device__ __forceinline__ int load_edge(const void* ei, long long idx, int is64) {
    if (is64) return (int)((const long long*)ei)[idx];
    return ((const int*)ei)[idx];
}

// -------------------------- CSR construction -------------------------------
__global__ void hist_kernel(const void* __restrict__ ei, int E, int N) {
    int e = blockIdx.x * blockDim.x + threadIdx.x;
    if (e < E) {
        int d = load_edge(ei, (long long)E + e, g_is64);
        if ((unsigned)d < (unsigned)N) atomicAdd(&g_deg[d], 1);
    }
}

// per-block exclusive scan (1024 elems/block), block totals -> g_bsums
__global__ void scan_block_kernel(int N) {
    __shared__ int sh[1024];
    int i = blockIdx.x * 1024 + threadIdx.x;
    int v = (i < N) ? g_deg[i] : 0;
    sh[threadIdx.x] = v;
    __syncthreads();
    for (int o = 1; o < 1024; o <<= 1) {
        int t = 0;
        if ((int)threadIdx.x >= o) t = sh[threadIdx.x - o];
        __syncthreads();
        sh[threadIdx.x] += t;
        __syncthreads();
    }
    int incl = sh[threadIdx.x];
    if (i < N) g_rowptr[i] = incl - v;            // exclusive within block
    if (threadIdx.x == 1023) g_bsums[blockIdx.x] = incl;
}

__global__ void scan_bsums_kernel(int nb) {
    if (threadIdx.x == 0 && blockIdx.x == 0) {
        int acc = 0;
        for (int b = 0; b < nb; b++) { int t = g_bsums[b]; g_bsums[b] = acc; acc += t; }
    }
}

__global__ void add_off_kernel(int N, int E) {
    int i = blockIdx.x * blockDim.x + threadIdx.x;
    if (i < N) {
        int v = g_rowptr[i] + g_bsums[i >> 10];
        g_rowptr[i] = v;
        g_cursor[i] = v;
    }
    if (i == 0) g_rowptr[N] = E;
}

__global__ void scatter_kernel(const void* __restrict__ ei, int E, int N) {
    int e = blockIdx.x * blockDim.x + threadIdx.x;
    if (e < E) {
        int is64 = g_is64;
        int d = load_edge(ei, (long long)E + e, is64);
        int s = load_edge(ei, e, is64);
        if ((unsigned)d < (unsigned)N && (unsigned)s < (unsigned)N) {
            int pos = atomicAdd(&g_cursor[d], 1);
            if ((unsigned)pos < (unsigned)E) g_esrc[pos] = s;
        }
    }
}

// --------------------------- fused projection -------------------------------
// Per node: h_src row (x@Wsrc), lin row (x@Wlin), a_src, a_dst.
// v = Wdst@attd folded per-block (64 threads, cheap). Scalar FFMA body (R12).
__global__ __launch_bounds__(256)
void proj_kernel(const float* __restrict__ xin_param,
                 const float* __restrict__ Wsrc,
                 const float* __restrict__ Wdst,
                 const float* __restrict__ Wlin,
                 const float* __restrict__ att_src,
                 const float* __restrict__ att_dst,
                 int from_gh, int N) {
    __shared__ float sWs[C * C];
    __shared__ float sWl[C * C];
    __shared__ float sAtt[C];
    __shared__ float sV[C];
    for (int i = threadIdx.x; i < C * C; i += 256) { sWs[i] = Wsrc[i]; sWl[i] = Wlin[i]; }
    if (threadIdx.x < C) {
        int k = threadIdx.x;
        float a = 0.f;
#pragma unroll 8
        for (int j = 0; j < C; j++) a += Wdst[k * C + j] * att_dst[j];
        sV[k] = a;
        sAtt[k] = att_src[k];
    }
    __syncthreads();

    int n = blockIdx.x * 256 + threadIdx.x;
    if (n >= N) return;

    const float* xin = from_gh ? g_h : xin_param;
    float xr[C];
    const float4* xp = (const float4*)(xin + (size_t)n * C);
#pragma unroll
    for (int k = 0; k < C / 4; k++) {
        float4 t = xp[k];
        xr[4 * k] = t.x; xr[4 * k + 1] = t.y; xr[4 * k + 2] = t.z; xr[4 * k + 3] = t.w;
    }

    float ad = 0.f;
#pragma unroll
    for (int k = 0; k < C; k++) ad += xr[k] * sV[k];
    g_adst[n] = ad;

    float as = 0.f;
    // h_src = xr @ Wsrc, a_src = h_src . att_src
    for (int jc = 0; jc < C; jc += 16) {
        float acc[16];
#pragma unroll
        for (int j = 0; j < 16; j++) acc[j] = 0.f;
#pragma unroll
        for (int k = 0; k < C; k++) {
            float xv = xr[k];
            const float4* wr = (const float4*)(sWs + k * C + jc);
#pragma unroll
            for (int j4 = 0; j4 < 4; j4++) {
                float4 w = wr[j4];
                acc[4 * j4]     += xv * w.x;
                acc[4 * j4 + 1] += xv * w.y;
                acc[4 * j4 + 2] += xv * w.z;
                acc[4 * j4 + 3] += xv * w.w;
            }
        }
        float4* hp = (float4*)(g_hsrc + (size_t)n * C + jc);
#pragma unroll
        for (int j4 = 0; j4 < 4; j4++)
            hp[j4] = make_float4(acc[4 * j4], acc[4 * j4 + 1], acc[4 * j4 + 2], acc[4 * j4 + 3]);
#pragma unroll
        for (int j = 0; j < 16; j++) as += acc[j] * sAtt[jc + j];
    }
    g_asrc[n] = as;

    // lin = xr @ Wlin
    for (int jc = 0; jc < C; jc += 16) {
        float acc[16];
#pragma unroll
        for (int j = 0; j < 16; j++) acc[j] = 0.f;
#pragma unroll
        for (int k = 0; k < C; k++) {
            float xv = xr[k];
            const float4* wr = (const float4*)(sWl + k * C + jc);
#pragma unroll
            for (int j4 = 0; j4 < 4; j4++) {
                float4 w = wr[j4];
                acc[4 * j4]     += xv * w.x;
                acc[4 * j4 + 1] += xv * w.y;
                acc[4 * j4 + 2] += xv * w.z;
                acc[4 * j4 + 3] += xv * w.w;
            }
        }
        float4* lp = (float4*)(g_lin + (size_t)n * C + jc);
#pragma unroll
        for (int j4 = 0; j4 < 4; j4++)
            lp[j4] = make_float4(acc[4 * j4], acc[4 * j4 + 1], acc[4 * j4 + 2], acc[4 * j4 + 3]);
    }
}

// ------------------------- edge aggregation ---------------------------------
// One warp per dst node. Single pass: w = exp(lrelu(e)) packed with src id into
// shared int2; warp-sum. Gather pass: lanes own 2 columns; acc += w*h_src[s].
// Epilogue fuses 1/sum, bias, residual, ReLU.
__global__ __launch_bounds__(256)
void edge_kernel(const float* __restrict__ bias,
                 const float* __restrict__ blin,
                 float* __restrict__ out_param,
                 int to_gh, int N) {
    __shared__ int2 sh_sw[8][SH_E];
    int wid  = threadIdx.x >> 5;
    int lane = threadIdx.x & 31;
    int n = blockIdx.x * 8 + wid;
    if (n >= N) return;

    int start = g_rowptr[n], end = g_rowptr[n + 1];
    int deg = end - start;

    float2 acc = make_float2(0.f, 0.f);
    float invs = 0.f;

    if (deg > 0) {
        float adn = g_adst[n];
        const float2* hp = (const float2*)g_hsrc;

        if (deg <= SH_E) {
            float sum = 0.f;
            for (int i = lane; i < deg; i += 32) {
                int s = g_esrc[start + i];
                float ev = g_asrc[s] + adn;
                ev = (ev >= 0.f) ? ev : 0.2f * ev;
                float w = __expf(ev);
                sh_sw[wid][i] = make_int2(s, __float_as_int(w));
                sum += w;
            }
#pragma unroll
            for (int o = 16; o > 0; o >>= 1) sum += __shfl_xor_sync(0xffffffff, sum, o);
            __syncwarp();

#pragma unroll 4
            for (int i = 0; i < deg; i++) {
                int2 sw = sh_sw[wid][i];
                float w = __int_as_float(sw.y);
                float2 hv = hp[(size_t)sw.x * 32 + lane];
                acc.x += w * hv.x;
                acc.y += w * hv.y;
            }
            invs = 1.f / sum;
        } else {
            float sum = 0.f;
            for (int i = lane; i < deg; i += 32) {
                int s = g_esrc[start + i];
                float ev = g_asrc[s] + adn;
                ev = (ev >= 0.f) ? ev : 0.2f * ev;
                sum += __expf(ev);
            }
#pragma unroll
            for (int o = 16; o > 0; o >>= 1) sum += __shfl_xor_sync(0xffffffff, sum, o);
            for (int i = 0; i < deg; i++) {
                int s = g_esrc[start + i];
                float ev = g_asrc[s] + adn;
                ev = (ev >= 0.f) ? ev : 0.2f * ev;
                float w = __expf(ev);
                float2 hv = hp[(size_t)s * 32 + lane];
                acc.x += w * hv.x;
                acc.y += w * hv.y;
            }
            invs = 1.f / sum;
        }
    }

    int c0 = 2 * lane;
    float2 lv = ((const float2*)(g_lin + (size_t)n * C))[lane];
    float v0 = acc.x * invs + bias[c0]     + lv.x + blin[c0];
    float v1 = acc.y * invs + bias[c0 + 1] + lv.y + blin[c0 + 1];
    v0 = fmaxf(v0, 0.f);
    v1 = fmaxf(v1, 0.f);
    float* op = to_gh ? g_h : out_param;
    ((float2*)(op + (size_t)n * C))[lane] = make_float2(v0, v1);
}

// ------------------------------- launch -------------------------------------
extern "C" void kernel_launch(void* const* d_in, const int* in_sizes, int n_in,
                              void* d_out, int out_size) {
    const float* x     = (const float*)d_in[0];
    const void*  ei    = d_in[1];
    const float* W1s   = (const float*)d_in[2];
    const float* W1d   = (const float*)d_in[3];
    const float* att1s = (const float*)d_in[4];
    const float* att1d = (const float*)d_in[5];
    const float* b1    = (const float*)d_in[6];
    const float* Wl1   = (const float*)d_in[7];
    const float* bl1   = (const float*)d_in[8];
    const float* W2s   = (const float*)d_in[9];
    const float* W2d   = (const float*)d_in[10];
    const float* att2s = (const float*)d_in[11];
    const float* att2d = (const float*)d_in[12];
    const float* b2    = (const float*)d_in[13];
    const float* Wl2   = (const float*)d_in[14];
    const float* bl2   = (const float*)d_in[15];
    float*       out   = (float*)d_out;

    int N = in_sizes[0] / C;         // 50000
    int E = in_sizes[1] / 2;         // 1200000

    int nbN  = (N + 255) / 256;
    int nbE  = (E + 255) / 256;
    int nbSc = (N + 1023) / 1024;
    int nbW  = (N + 7) / 8;

    // ---- CSR build (shared by both layers) ----
    init_kernel<<<nbN, 256>>>((const long long*)ei, N);
    hist_kernel<<<nbE, 256>>>(ei, E, N);
    scan_block_kernel<<<nbSc, 1024>>>(N);
    scan_bsums_kernel<<<1, 32>>>(nbSc);
    add_off_kernel<<<nbN, 256>>>(N, E);
    scatter_kernel<<<nbE, 256>>>(ei, E, N);

    // ---- layer 1: x -> g_h ----
    proj_kernel<<<nbN, 256>>>(x, W1s, W1d, Wl1, att1s, att1d, /*from_gh=*/0, N);
    edge_kernel<<<nbW, 256>>>(b1, bl1, out, /*to_gh=*/1, N);

    // ---- layer 2: g_h -> out ----
    proj_kernel<<<nbN, 256>>>(x, W2s, W2d, Wl2, att2s, att2d, /*from_gh=*/1, N);
    edge_kernel<<<nbW, 256>>>(b2, bl2, out, /*to_gh=*/0, N);
}

// round 15
// speedup vs baseline: 1.4435x; 1.1368x over previous
#include <cuda_runtime.h>
#include <cuda_bf16.h>

// ---------------------------------------------------------------------------
// GAT (2 layers, heads=1) on GB300 — R15.
// R14 (206.8us) + : side-stream fork/join so CSR build overlaps proj1;
// 4-edge ILP in hist/scatter (they were latency-bound, issue=7.3%);
// warp-shuffle scan; bsums prefix folded into add_off (serial 5.4us kernel gone).
// ---------------------------------------------------------------------------

#define NMAX 50000
#define EMAX 1200000
#define C    64
#define SH_E 256   // max in-degree on fast shared path (Poisson(24) -> never exceeded)

// -------------------- scratch (device globals; no allocs) ------------------
__device__ float g_hsrc[NMAX * C];
__device__ float g_lin [NMAX * C];
__device__ float g_h   [NMAX * C];
__device__ float g_asrc[NMAX];
__device__ float g_adst[NMAX];
__device__ int   g_deg   [NMAX];
__device__ int   g_rowptr[NMAX + 1];
__device__ int   g_cursor[NMAX];
__device__ int   g_esrc  [EMAX];
__device__ int   g_bsums [64];
__device__ int   g_is64;

// ------------------ init: zero deg + PARALLEL dtype detect ------------------
// int32 data misread as int64 pairs two random indices -> almost surely >= N.
__global__ void init_kernel(const long long* __restrict__ ei, int N) {
    int i = blockIdx.x * blockDim.x + threadIdx.x;
    if (i < N) g_deg[i] = 0;
    if (blockIdx.x == 0 && threadIdx.x < 32) {
        long long v0 = ei[threadIdx.x];
        long long v1 = ei[32 + threadIdx.x];
        int bad = (v0 < 0 || v0 >= N || v1 < 0 || v1 >= N) ? 1 : 0;
        unsigned m = __ballot_sync(0xffffffff, bad);
        if (threadIdx.x == 0) g_is64 = (m == 0u) ? 1 : 0;
    }
}

__device__ __forceinline__ int load_edge(const void* ei, long long idx, int is64) {
    if (is64) return (int)((const long long*)ei)[idx];
    return ((const int*)ei)[idx];
}

// Load 4 consecutive edge ids starting at idx0 (idx0 % 4 == 0).
__device__ __forceinline__ void load_edge4(const void* ei, long long idx0,
                                           int is64, int d[4]) {
    if (is64) {
        const int4* p = (const int4*)((const long long*)ei + idx0);
        int4 a = p[0], b = p[1];          // low words of little-endian int64s
        d[0] = a.x; d[1] = a.z; d[2] = b.x; d[3] = b.z;
    } else {
        int4 a = *(const int4*)((const int*)ei + idx0);
        d[0] = a.x; d[1] = a.y; d[2] = a.z; d[3] = a.w;
    }
}

// -------------------------- CSR construction -------------------------------
// 4 edges/thread for MLP (these kernels were latency-bound at issue=7.3%).
__global__ void hist_kernel(const void* __restrict__ ei, int E, int N) {
    int base = (blockIdx.x * blockDim.x + threadIdx.x) * 4;
    if (base >= E) return;
    int is64 = g_is64;
    if (base + 3 < E) {
        int d[4];
        load_edge4(ei, (long long)E + base, is64, d);
#pragma unroll
        for (int j = 0; j < 4; j++)
            if ((unsigned)d[j] < (unsigned)N) atomicAdd(&g_deg[d[j]], 1);
    } else {
        for (int e = base; e < E; e++) {
            int d = load_edge(ei, (long long)E + e, is64);
            if ((unsigned)d < (unsigned)N) atomicAdd(&g_deg[d], 1);
        }
    }
}

// per-block exclusive scan (1024 elems/block) via warp shuffles.
__global__ __launch_bounds__(1024)
void scan_block_kernel(int N) {
    __shared__ int wsum[32];
    int i = blockIdx.x * 1024 + threadIdx.x;
    int lane = threadIdx.x & 31, wid = threadIdx.x >> 5;
    int v = (i < N) ? g_deg[i] : 0;
    int x = v;
#pragma unroll
    for (int o = 1; o < 32; o <<= 1) {
        int t = __shfl_up_sync(0xffffffff, x, o);
        if (lane >= o) x += t;
    }
    if (lane == 31) wsum[wid] = x;
    __syncthreads();
    if (wid == 0) {
        int s = wsum[lane];
#pragma unroll
        for (int o = 1; o < 32; o <<= 1) {
            int t = __shfl_up_sync(0xffffffff, s, o);
            if (lane >= o) s += t;
        }
        wsum[lane] = s;
    }
    __syncthreads();
    int base = wid ? wsum[wid - 1] : 0;
    if (i < N) g_rowptr[i] = base + x - v;           // block-local exclusive
    if (threadIdx.x == 1023) g_bsums[blockIdx.x] = base + x;   // block total
}

// add global offset: each 256-thread block needs prefix of bsums[0 .. bIdx/4).
// One warp reduces (<= 49 values); no serial kernel needed.
__global__ void add_off_kernel(int N, int E) {
    __shared__ int s_pre;
    int nb = blockIdx.x >> 2;
    if (threadIdx.x < 32) {
        int acc = 0;
        for (int j = threadIdx.x; j < nb; j += 32) acc += g_bsums[j];
#pragma unroll
        for (int o = 16; o > 0; o >>= 1) acc += __shfl_xor_sync(0xffffffff, acc, o);
        if (threadIdx.x == 0) s_pre = acc;
    }
    __syncthreads();
    int i = blockIdx.x * 256 + threadIdx.x;
    if (i < N) {
        int v = g_rowptr[i] + s_pre;
        g_rowptr[i] = v;
        g_cursor[i] = v;
    }
    if (i == 0) g_rowptr[N] = E;
}

__global__ void scatter_kernel(const void* __restrict__ ei, int E, int N) {
    int base = (blockIdx.x * blockDim.x + threadIdx.x) * 4;
    if (base >= E) return;
    int is64 = g_is64;
    if (base + 3 < E) {
        int d[4], s[4];
        load_edge4(ei, (long long)E + base, is64, d);
        load_edge4(ei, (long long)base, is64, s);
#pragma unroll
        for (int j = 0; j < 4; j++) {
            if ((unsigned)d[j] < (unsigned)N && (unsigned)s[j] < (unsigned)N) {
                int pos = atomicAdd(&g_cursor[d[j]], 1);
                if ((unsigned)pos < (unsigned)E) g_esrc[pos] = s[j];
            }
        }
    } else {
        for (int e = base; e < E; e++) {
            int d = load_edge(ei, (long long)E + e, is64);
            int s = load_edge(ei, e, is64);
            if ((unsigned)d < (unsigned)N && (unsigned)s < (unsigned)N) {
                int pos = atomicAdd(&g_cursor[d], 1);
                if ((unsigned)pos < (unsigned)E) g_esrc[pos] = s;
            }
        }
    }
}

// --------------------------- fused projection -------------------------------
// Per node: h_src row (x@Wsrc), lin row (x@Wlin), a_src, a_dst.
// v = Wdst@attd folded per-block. Scalar FFMA body (known-good R12 form).
__global__ __launch_bounds__(256)
void proj_kernel(const float* __restrict__ xin_param,
                 const float* __restrict__ Wsrc,
                 const float* __restrict__ Wdst,
                 const float* __restrict__ Wlin,
                 const float* __restrict__ att_src,
                 const float* __restrict__ att_dst,
                 int from_gh, int N) {
    __shared__ float sWs[C * C];
    __shared__ float sWl[C * C];
    __shared__ float sAtt[C];
    __shared__ float sV[C];
    for (int i = threadIdx.x; i < C * C; i += 256) { sWs[i] = Wsrc[i]; sWl[i] = Wlin[i]; }
    if (threadIdx.x < C) {
        int k = threadIdx.x;
        float a = 0.f;
#pragma unroll 8
        for (int j = 0; j < C; j++) a += Wdst[k * C + j] * att_dst[j];
        sV[k] = a;
        sAtt[k] = att_src[k];
    }
    __syncthreads();

    int n = blockIdx.x * 256 + threadIdx.x;
    if (n >= N) return;

    const float* xin = from_gh ? g_h : xin_param;
    float xr[C];
    const float4* xp = (const float4*)(xin + (size_t)n * C);
#pragma unroll
    for (int k = 0; k < C / 4; k++) {
        float4 t = xp[k];
        xr[4 * k] = t.x; xr[4 * k + 1] = t.y; xr[4 * k + 2] = t.z; xr[4 * k + 3] = t.w;
    }

    float ad = 0.f;
#pragma unroll
    for (int k = 0; k < C; k++) ad += xr[k] * sV[k];
    g_adst[n] = ad;

    float as = 0.f;
    // h_src = xr @ Wsrc, a_src = h_src . att_src
    for (int jc = 0; jc < C; jc += 16) {
        float acc[16];
#pragma unroll
        for (int j = 0; j < 16; j++) acc[j] = 0.f;
#pragma unroll
        for (int k = 0; k < C; k++) {
            float xv = xr[k];
            const float4* wr = (const float4*)(sWs + k * C + jc);
#pragma unroll
            for (int j4 = 0; j4 < 4; j4++) {
                float4 w = wr[j4];
                acc[4 * j4]     += xv * w.x;
                acc[4 * j4 + 1] += xv * w.y;
                acc[4 * j4 + 2] += xv * w.z;
                acc[4 * j4 + 3] += xv * w.w;
            }
        }
        float4* hp = (float4*)(g_hsrc + (size_t)n * C + jc);
#pragma unroll
        for (int j4 = 0; j4 < 4; j4++)
            hp[j4] = make_float4(acc[4 * j4], acc[4 * j4 + 1], acc[4 * j4 + 2], acc[4 * j4 + 3]);
#pragma unroll
        for (int j = 0; j < 16; j++) as += acc[j] * sAtt[jc + j];
    }
    g_asrc[n] = as;

    // lin = xr @ Wlin
    for (int jc = 0; jc < C; jc += 16) {
        float acc[16];
#pragma unroll
        for (int j = 0; j < 16; j++) acc[j] = 0.f;
#pragma unroll
        for (int k = 0; k < C; k++) {
            float xv = xr[k];
            const float4* wr = (const float4*)(sWl + k * C + jc);
#pragma unroll
            for (int j4 = 0; j4 < 4; j4++) {
                float4 w = wr[j4];
                acc[4 * j4]     += xv * w.x;
                acc[4 * j4 + 1] += xv * w.y;
                acc[4 * j4 + 2] += xv * w.z;
                acc[4 * j4 + 3] += xv * w.w;
            }
        }
        float4* lp = (float4*)(g_lin + (size_t)n * C + jc);
#pragma unroll
        for (int j4 = 0; j4 < 4; j4++)
            lp[j4] = make_float4(acc[4 * j4], acc[4 * j4 + 1], acc[4 * j4 + 2], acc[4 * j4 + 3]);
    }
}

// ------------------------- edge aggregation ---------------------------------
// One warp per dst node. Single pass: w = exp(lrelu(e)) packed with src id into
// shared int2; warp-sum. Gather pass: lanes own 2 columns; acc += w*h_src[s].
// Epilogue fuses 1/sum, bias, residual, ReLU.
__global__ __launch_bounds__(256)
void edge_kernel(const float* __restrict__ bias,
                 const float* __restrict__ blin,
                 float* __restrict__ out_param,
                 int to_gh, int N) {
    __shared__ int2 sh_sw[8][SH_E];
    int wid  = threadIdx.x >> 5;
    int lane = threadIdx.x & 31;
    int n = blockIdx.x * 8 + wid;
    if (n >= N) return;

    int start = g_rowptr[n], end = g_rowptr[n + 1];
    int deg = end - start;

    float2 acc = make_float2(0.f, 0.f);
    float invs = 0.f;

    if (deg > 0) {
        float adn = g_adst[n];
        const float2* hp = (const float2*)g_hsrc;

        if (deg <= SH_E) {
            float sum = 0.f;
            for (int i = lane; i < deg; i += 32) {
                int s = g_esrc[start + i];
                float ev = g_asrc[s] + adn;
                ev = (ev >= 0.f) ? ev : 0.2f * ev;
                float w = __expf(ev);
                sh_sw[wid][i] = make_int2(s, __float_as_int(w));
                sum += w;
            }
#pragma unroll
            for (int o = 16; o > 0; o >>= 1) sum += __shfl_xor_sync(0xffffffff, sum, o);
            __syncwarp();

#pragma unroll 4
            for (int i = 0; i < deg; i++) {
                int2 sw = sh_sw[wid][i];
                float w = __int_as_float(sw.y);
                float2 hv = hp[(size_t)sw.x * 32 + lane];
                acc.x += w * hv.x;
                acc.y += w * hv.y;
            }
            invs = 1.f / sum;
        } else {
            float sum = 0.f;
            for (int i = lane; i < deg; i += 32) {
                int s = g_esrc[start + i];
                float ev = g_asrc[s] + adn;
                ev = (ev >= 0.f) ? ev : 0.2f * ev;
                sum += __expf(ev);
            }
#pragma unroll
            for (int o = 16; o > 0; o >>= 1) sum += __shfl_xor_sync(0xffffffff, sum, o);
            for (int i = 0; i < deg; i++) {
                int s = g_esrc[start + i];
                float ev = g_asrc[s] + adn;
                ev = (ev >= 0.f) ? ev : 0.2f * ev;
                float w = __expf(ev);
                float2 hv = hp[(size_t)s * 32 + lane];
                acc.x += w * hv.x;
                acc.y += w * hv.y;
            }
            invs = 1.f / sum;
        }
    }

    int c0 = 2 * lane;
    float2 lv = ((const float2*)(g_lin + (size_t)n * C))[lane];
    float v0 = acc.x * invs + bias[c0]     + lv.x + blin[c0];
    float v1 = acc.y * invs + bias[c0 + 1] + lv.y + blin[c0 + 1];
    v0 = fmaxf(v0, 0.f);
    v1 = fmaxf(v1, 0.f);
    float* op = to_gh ? g_h : out_param;
    ((float2*)(op + (size_t)n * C))[lane] = make_float2(v0, v1);
}

// ------------------------------- launch -------------------------------------
extern "C" void kernel_launch(void* const* d_in, const int* in_sizes, int n_in,
                              void* d_out, int out_size) {
    const float* x     = (const float*)d_in[0];
    const void*  ei    = d_in[1];
    const float* W1s   = (const float*)d_in[2];
    const float* W1d   = (const float*)d_in[3];
    const float* att1s = (const float*)d_in[4];
    const float* att1d = (const float*)d_in[5];
    const float* b1    = (const float*)d_in[6];
    const float* Wl1   = (const float*)d_in[7];
    const float* bl1   = (const float*)d_in[8];
    const float* W2s   = (const float*)d_in[9];
    const float* W2d   = (const float*)d_in[10];
    const float* att2s = (const float*)d_in[11];
    const float* att2d = (const float*)d_in[12];
    const float* b2    = (const float*)d_in[13];
    const float* Wl2   = (const float*)d_in[14];
    const float* bl2   = (const float*)d_in[15];
    float*       out   = (float*)d_out;

    int N = in_sizes[0] / C;         // 50000
    int E = in_sizes[1] / 2;         // 1200000

    int nbN  = (N + 255) / 256;
    int nbE4 = (E / 4 + 255) / 256;  // 4 edges per thread
    int nbSc = (N + 1023) / 1024;
    int nbW  = (N + 7) / 8;

    // One side stream + fork/join events (created on the eager correctness
    // call, i.e. before graph capture; reused identically on every call).
    static cudaStream_t side = nullptr;
    static cudaEvent_t  evFork = nullptr, evJoin = nullptr;
    if (side == nullptr) {
        cudaStreamCreateWithFlags(&side, cudaStreamNonBlocking);
        cudaEventCreateWithFlags(&evFork, cudaEventDisableTiming);
        cudaEventCreateWithFlags(&evJoin, cudaEventDisableTiming);
    }

    // ---- fork: CSR build on side stream, proj1 on main stream ----
    cudaEventRecord(evFork, 0);
    cudaStreamWaitEvent(side, evFork, 0);

    init_kernel   <<<nbN,  256, 0, side>>>((const long long*)ei, N);
    hist_kernel   <<<nbE4, 256, 0, side>>>(ei, E, N);
    scan_block_kernel<<<nbSc, 1024, 0, side>>>(N);
    add_off_kernel<<<nbN,  256, 0, side>>>(N, E);
    scatter_kernel<<<nbE4, 256, 0, side>>>(ei, E, N);
    cudaEventRecord(evJoin, side);

    proj_kernel<<<nbN, 256>>>(x, W1s, W1d, Wl1, att1s, att1d, /*from_gh=*/0, N);

    // ---- join, then the serial tail ----
    cudaStreamWaitEvent(0, evJoin, 0);
    edge_kernel<<<nbW, 256>>>(b1, bl1, out, /*to_gh=*/1, N);
    proj_kernel<<<nbN, 256>>>(x, W2s, W2d, Wl2, att2s, att2d, /*from_gh=*/1, N);
    edge_kernel<<<nbW, 256>>>(b2, bl2, out, /*to_gh=*/0, N);
}

// round 16
// speedup vs baseline: 1.5072x; 1.0441x over previous
#include <cuda_runtime.h>
#include <cuda_bf16.h>
#include <cuda_fp16.h>

// ---------------------------------------------------------------------------
// GAT (2 layers, heads=1) on GB300 — R16.
// R15 (182.0us) + fp16 h_src storage: edge gather traffic halved (256B -> 128B
// per edge). Aggregation stays fp32; residual/bias/g_h stay fp32.
// ---------------------------------------------------------------------------

#define NMAX 50000
#define EMAX 1200000
#define C    64
#define SH_E 256   // max in-degree on fast shared path (Poisson(24) -> never exceeded)

// -------------------- scratch (device globals; no allocs) ------------------
__device__ __half2 g_hsrch[NMAX * (C / 2)];   // h_src rows, fp16 pairs
__device__ float g_lin [NMAX * C];
__device__ float g_h   [NMAX * C];
__device__ float g_asrc[NMAX];
__device__ float g_adst[NMAX];
__device__ int   g_deg   [NMAX];
__device__ int   g_rowptr[NMAX + 1];
__device__ int   g_cursor[NMAX];
__device__ int   g_esrc  [EMAX];
__device__ int   g_bsums [64];
__device__ int   g_is64;

// ------------------ init: zero deg + PARALLEL dtype detect ------------------
__global__ void init_kernel(const long long* __restrict__ ei, int N) {
    int i = blockIdx.x * blockDim.x + threadIdx.x;
    if (i < N) g_deg[i] = 0;
    if (blockIdx.x == 0 && threadIdx.x < 32) {
        long long v0 = ei[threadIdx.x];
        long long v1 = ei[32 + threadIdx.x];
        int bad = (v0 < 0 || v0 >= N || v1 < 0 || v1 >= N) ? 1 : 0;
        unsigned m = __ballot_sync(0xffffffff, bad);
        if (threadIdx.x == 0) g_is64 = (m == 0u) ? 1 : 0;
    }
}

__device__ __forceinline__ int load_edge(const void* ei, long long idx, int is64) {
    if (is64) return (int)((const long long*)ei)[idx];
    return ((const int*)ei)[idx];
}

__device__ __forceinline__ void load_edge4(const void* ei, long long idx0,
                                           int is64, int d[4]) {
    if (is64) {
        const int4* p = (const int4*)((const long long*)ei + idx0);
        int4 a = p[0], b = p[1];          // low words of little-endian int64s
        d[0] = a.x; d[1] = a.z; d[2] = b.x; d[3] = b.z;
    } else {
        int4 a = *(const int4*)((const int*)ei + idx0);
        d[0] = a.x; d[1] = a.y; d[2] = a.z; d[3] = a.w;
    }
}

// -------------------------- CSR construction -------------------------------
__global__ void hist_kernel(const void* __restrict__ ei, int E, int N) {
    int base = (blockIdx.x * blockDim.x + threadIdx.x) * 4;
    if (base >= E) return;
    int is64 = g_is64;
    if (base + 3 < E) {
        int d[4];
        load_edge4(ei, (long long)E + base, is64, d);
#pragma unroll
        for (int j = 0; j < 4; j++)
            if ((unsigned)d[j] < (unsigned)N) atomicAdd(&g_deg[d[j]], 1);
    } else {
        for (int e = base; e < E; e++) {
            int d = load_edge(ei, (long long)E + e, is64);
            if ((unsigned)d < (unsigned)N) atomicAdd(&g_deg[d], 1);
        }
    }
}

__global__ __launch_bounds__(1024)
void scan_block_kernel(int N) {
    __shared__ int wsum[32];
    int i = blockIdx.x * 1024 + threadIdx.x;
    int lane = threadIdx.x & 31, wid = threadIdx.x >> 5;
    int v = (i < N) ? g_deg[i] : 0;
    int x = v;
#pragma unroll
    for (int o = 1; o < 32; o <<= 1) {
        int t = __shfl_up_sync(0xffffffff, x, o);
        if (lane >= o) x += t;
    }
    if (lane == 31) wsum[wid] = x;
    __syncthreads();
    if (wid == 0) {
        int s = wsum[lane];
#pragma unroll
        for (int o = 1; o < 32; o <<= 1) {
            int t = __shfl_up_sync(0xffffffff, s, o);
            if (lane >= o) s += t;
        }
        wsum[lane] = s;
    }
    __syncthreads();
    int base = wid ? wsum[wid - 1] : 0;
    if (i < N) g_rowptr[i] = base + x - v;
    if (threadIdx.x == 1023) g_bsums[blockIdx.x] = base + x;
}

__global__ void add_off_kernel(int N, int E) {
    __shared__ int s_pre;
    int nb = blockIdx.x >> 2;
    if (threadIdx.x < 32) {
        int acc = 0;
        for (int j = threadIdx.x; j < nb; j += 32) acc += g_bsums[j];
#pragma unroll
        for (int o = 16; o > 0; o >>= 1) acc += __shfl_xor_sync(0xffffffff, acc, o);
        if (threadIdx.x == 0) s_pre = acc;
    }
    __syncthreads();
    int i = blockIdx.x * 256 + threadIdx.x;
    if (i < N) {
        int v = g_rowptr[i] + s_pre;
        g_rowptr[i] = v;
        g_cursor[i] = v;
    }
    if (i == 0) g_rowptr[N] = E;
}

__global__ void scatter_kernel(const void* __restrict__ ei, int E, int N) {
    int base = (blockIdx.x * blockDim.x + threadIdx.x) * 4;
    if (base >= E) return;
    int is64 = g_is64;
    if (base + 3 < E) {
        int d[4], s[4];
        load_edge4(ei, (long long)E + base, is64, d);
        load_edge4(ei, (long long)base, is64, s);
#pragma unroll
        for (int j = 0; j < 4; j++) {
            if ((unsigned)d[j] < (unsigned)N && (unsigned)s[j] < (unsigned)N) {
                int pos = atomicAdd(&g_cursor[d[j]], 1);
                if ((unsigned)pos < (unsigned)E) g_esrc[pos] = s[j];
            }
        }
    } else {
        for (int e = base; e < E; e++) {
            int d = load_edge(ei, (long long)E + e, is64);
            int s = load_edge(ei, e, is64);
            if ((unsigned)d < (unsigned)N && (unsigned)s < (unsigned)N) {
                int pos = atomicAdd(&g_cursor[d], 1);
                if ((unsigned)pos < (unsigned)E) g_esrc[pos] = s;
            }
        }
    }
}

// --------------------------- fused projection -------------------------------
// Per node: h_src row (fp32 math, fp16 store), lin row (fp32), a_src, a_dst.
__global__ __launch_bounds__(256)
void proj_kernel(const float* __restrict__ xin_param,
                 const float* __restrict__ Wsrc,
                 const float* __restrict__ Wdst,
                 const float* __restrict__ Wlin,
                 const float* __restrict__ att_src,
                 const float* __restrict__ att_dst,
                 int from_gh, int N) {
    __shared__ float sWs[C * C];
    __shared__ float sWl[C * C];
    __shared__ float sAtt[C];
    __shared__ float sV[C];
    for (int i = threadIdx.x; i < C * C; i += 256) { sWs[i] = Wsrc[i]; sWl[i] = Wlin[i]; }
    if (threadIdx.x < C) {
        int k = threadIdx.x;
        float a = 0.f;
#pragma unroll 8
        for (int j = 0; j < C; j++) a += Wdst[k * C + j] * att_dst[j];
        sV[k] = a;
        sAtt[k] = att_src[k];
    }
    __syncthreads();

    int n = blockIdx.x * 256 + threadIdx.x;
    if (n >= N) return;

    const float* xin = from_gh ? g_h : xin_param;
    float xr[C];
    const float4* xp = (const float4*)(xin + (size_t)n * C);
#pragma unroll
    for (int k = 0; k < C / 4; k++) {
        float4 t = xp[k];
        xr[4 * k] = t.x; xr[4 * k + 1] = t.y; xr[4 * k + 2] = t.z; xr[4 * k + 3] = t.w;
    }

    float ad = 0.f;
#pragma unroll
    for (int k = 0; k < C; k++) ad += xr[k] * sV[k];
    g_adst[n] = ad;

    float as = 0.f;
    // h_src = xr @ Wsrc (fp32), stored as half2 pairs; a_src = h_src . att_src
    for (int jc = 0; jc < C; jc += 16) {
        float acc[16];
#pragma unroll
        for (int j = 0; j < 16; j++) acc[j] = 0.f;
#pragma unroll
        for (int k = 0; k < C; k++) {
            float xv = xr[k];
            const float4* wr = (const float4*)(sWs + k * C + jc);
#pragma unroll
            for (int j4 = 0; j4 < 4; j4++) {
                float4 w = wr[j4];
                acc[4 * j4]     += xv * w.x;
                acc[4 * j4 + 1] += xv * w.y;
                acc[4 * j4 + 2] += xv * w.z;
                acc[4 * j4 + 3] += xv * w.w;
            }
        }
        union { __half2 h2[8]; uint4 u4[2]; } pk;
#pragma unroll
        for (int j2 = 0; j2 < 8; j2++)
            pk.h2[j2] = __floats2half2_rn(acc[2 * j2], acc[2 * j2 + 1]);
        uint4* hp = (uint4*)(g_hsrch + (size_t)n * (C / 2) + jc / 2);
        hp[0] = pk.u4[0];
        hp[1] = pk.u4[1];
#pragma unroll
        for (int j = 0; j < 16; j++) as += acc[j] * sAtt[jc + j];
    }
    g_asrc[n] = as;

    // lin = xr @ Wlin (fp32)
    for (int jc = 0; jc < C; jc += 16) {
        float acc[16];
#pragma unroll
        for (int j = 0; j < 16; j++) acc[j] = 0.f;
#pragma unroll
        for (int k = 0; k < C; k++) {
            float xv = xr[k];
            const float4* wr = (const float4*)(sWl + k * C + jc);
#pragma unroll
            for (int j4 = 0; j4 < 4; j4++) {
                float4 w = wr[j4];
                acc[4 * j4]     += xv * w.x;
                acc[4 * j4 + 1] += xv * w.y;
                acc[4 * j4 + 2] += xv * w.z;
                acc[4 * j4 + 3] += xv * w.w;
            }
        }
        float4* lp = (float4*)(g_lin + (size_t)n * C + jc);
#pragma unroll
        for (int j4 = 0; j4 < 4; j4++)
            lp[j4] = make_float4(acc[4 * j4], acc[4 * j4 + 1], acc[4 * j4 + 2], acc[4 * j4 + 3]);
    }
}

// ------------------------- edge aggregation ---------------------------------
// One warp per dst node. Gather reads fp16 half2 rows (128B/edge), accumulates
// fp32. Epilogue fuses 1/sum, bias, residual, ReLU.
__global__ __launch_bounds__(256)
void edge_kernel(const float* __restrict__ bias,
                 const float* __restrict__ blin,
                 float* __restrict__ out_param,
                 int to_gh, int N) {
    __shared__ int2 sh_sw[8][SH_E];
    int wid  = threadIdx.x >> 5;
    int lane = threadIdx.x & 31;
    int n = blockIdx.x * 8 + wid;
    if (n >= N) return;

    int start = g_rowptr[n], end = g_rowptr[n + 1];
    int deg = end - start;

    float2 acc = make_float2(0.f, 0.f);
    float invs = 0.f;

    if (deg > 0) {
        float adn = g_adst[n];
        const __half2* hp = g_hsrch;

        if (deg <= SH_E) {
            float sum = 0.f;
            for (int i = lane; i < deg; i += 32) {
                int s = g_esrc[start + i];
                float ev = g_asrc[s] + adn;
                ev = (ev >= 0.f) ? ev : 0.2f * ev;
                float w = __expf(ev);
                sh_sw[wid][i] = make_int2(s, __float_as_int(w));
                sum += w;
            }
#pragma unroll
            for (int o = 16; o > 0; o >>= 1) sum += __shfl_xor_sync(0xffffffff, sum, o);
            __syncwarp();

#pragma unroll 4
            for (int i = 0; i < deg; i++) {
                int2 sw = sh_sw[wid][i];
                float w = __int_as_float(sw.y);
                float2 hv = __half22float2(hp[(size_t)sw.x * 32 + lane]);
                acc.x += w * hv.x;
                acc.y += w * hv.y;
            }
            invs = 1.f / sum;
        } else {
            float sum = 0.f;
            for (int i = lane; i < deg; i += 32) {
                int s = g_esrc[start + i];
                float ev = g_asrc[s] + adn;
                ev = (ev >= 0.f) ? ev : 0.2f * ev;
                sum += __expf(ev);
            }
#pragma unroll
            for (int o = 16; o > 0; o >>= 1) sum += __shfl_xor_sync(0xffffffff, sum, o);
            for (int i = 0; i < deg; i++) {
                int s = g_esrc[start + i];
                float ev = g_asrc[s] + adn;
                ev = (ev >= 0.f) ? ev : 0.2f * ev;
                float w = __expf(ev);
                float2 hv = __half22float2(hp[(size_t)s * 32 + lane]);
                acc.x += w * hv.x;
                acc.y += w * hv.y;
            }
            invs = 1.f / sum;
        }
    }

    int c0 = 2 * lane;
    float2 lv = ((const float2*)(g_lin + (size_t)n * C))[lane];
    float v0 = acc.x * invs + bias[c0]     + lv.x + blin[c0];
    float v1 = acc.y * invs + bias[c0 + 1] + lv.y + blin[c0 + 1];
    v0 = fmaxf(v0, 0.f);
    v1 = fmaxf(v1, 0.f);
    float* op = to_gh ? g_h : out_param;
    ((float2*)(op + (size_t)n * C))[lane] = make_float2(v0, v1);
}

// ------------------------------- launch -------------------------------------
extern "C" void kernel_launch(void* const* d_in, const int* in_sizes, int n_in,
                              void* d_out, int out_size) {
    const float* x     = (const float*)d_in[0];
    const void*  ei    = d_in[1];
    const float* W1s   = (const float*)d_in[2];
    const float* W1d   = (const float*)d_in[3];
    const float* att1s = (const float*)d_in[4];
    const float* att1d = (const float*)d_in[5];
    const float* b1    = (const float*)d_in[6];
    const float* Wl1   = (const float*)d_in[7];
    const float* bl1   = (const float*)d_in[8];
    const float* W2s   = (const float*)d_in[9];
    const float* W2d   = (const float*)d_in[10];
    const float* att2s = (const float*)d_in[11];
    const float* att2d = (const float*)d_in[12];
    const float* b2    = (const float*)d_in[13];
    const float* Wl2   = (const float*)d_in[14];
    const float* bl2   = (const float*)d_in[15];
    float*       out   = (float*)d_out;

    int N = in_sizes[0] / C;         // 50000
    int E = in_sizes[1] / 2;         // 1200000

    int nbN  = (N + 255) / 256;
    int nbE4 = (E / 4 + 255) / 256;  // 4 edges per thread
    int nbSc = (N + 1023) / 1024;
    int nbW  = (N + 7) / 8;

    // One side stream + fork/join events (created on the eager correctness
    // call, i.e. before graph capture; reused identically on every call).
    static cudaStream_t side = nullptr;
    static cudaEvent_t  evFork = nullptr, evJoin = nullptr;
    if (side == nullptr) {
        cudaStreamCreateWithFlags(&side, cudaStreamNonBlocking);
        cudaEventCreateWithFlags(&evFork, cudaEventDisableTiming);
        cudaEventCreateWithFlags(&evJoin, cudaEventDisableTiming);
    }

    // ---- fork: CSR build on side stream, proj1 on main stream ----
    cudaEventRecord(evFork, 0);
    cudaStreamWaitEvent(side, evFork, 0);

    init_kernel      <<<nbN,  256, 0, side>>>((const long long*)ei, N);
    hist_kernel      <<<nbE4, 256, 0, side>>>(ei, E, N);
    scan_block_kernel<<<nbSc, 1024, 0, side>>>(N);
    add_off_kernel   <<<nbN,  256, 0, side>>>(N, E);
    scatter_kernel   <<<nbE4, 256, 0, side>>>(ei, E, N);
    cudaEventRecord(evJoin, side);

    proj_kernel<<<nbN, 256>>>(x, W1s, W1d, Wl1, att1s, att1d, /*from_gh=*/0, N);

    // ---- join, then the serial tail ----
    cudaStreamWaitEvent(0, evJoin, 0);
    edge_kernel<<<nbW, 256>>>(b1, bl1, out, /*to_gh=*/1, N);
    proj_kernel<<<nbN, 256>>>(x, W2s, W2d, Wl2, att2s, att2d, /*from_gh=*/1, N);
    edge_kernel<<<nbW, 256>>>(b2, bl2, out, /*to_gh=*/0, N);
}